// round 1
// baseline (speedup 1.0000x reference)
#include <cuda_runtime.h>
#include <cstdint>

// Problem constants (dataset-fixed; node/edge counts read at runtime)
#define MAX_NODES 50000
#define LAT       100
#define NGRAPH    256
#define H2        200
#define NCLASS    55

// ---------------- scratch (device globals: no allocation allowed) ----------
__device__ __align__(16) float g_bufA[MAX_NODES * LAT];
__device__ __align__(16) float g_bufB[MAX_NODES * LAT];
__device__ __align__(16) float g_inv_out[MAX_NODES];
__device__ __align__(16) float g_inv_in[MAX_NODES];
__device__ __align__(16) float g_pool[NGRAPH * H2];
__device__ __align__(16) float g_cnt[NGRAPH];

// ---------------- small kernels -------------------------------------------
__global__ void zero_kernel(float4* p, int n4) {
    int i = blockIdx.x * blockDim.x + threadIdx.x;
    float4 z = make_float4(0.f, 0.f, 0.f, 0.f);
    for (; i < n4; i += gridDim.x * blockDim.x) p[i] = z;
}

__global__ void degree_kernel(const int* __restrict__ src, const int* __restrict__ dst, int E) {
    int i = blockIdx.x * blockDim.x + threadIdx.x;
    if (i < E) {
        atomicAdd(&g_inv_out[src[i]], 1.0f);
        atomicAdd(&g_inv_in[dst[i]], 1.0f);
    }
}

__global__ void rsqrt_kernel(int n) {
    int i = blockIdx.x * blockDim.x + threadIdx.x;
    if (i < n) {
        g_inv_out[i] = rsqrtf(fmaxf(g_inv_out[i], 1.0f));
        g_inv_in[i]  = rsqrtf(fmaxf(g_inv_in[i], 1.0f));
    }
}

__global__ void count_kernel(const int* __restrict__ gid, int n) {
    int i = blockIdx.x * blockDim.x + threadIdx.x;
    if (i < n) atomicAdd(&g_cnt[gid[i]], 1.0f);
}

// ---------------- edge propagation: agg[dst] += xs[src] (100 f32 per edge) -
// One thread per (edge, float4-chunk). 25 chunks per edge.
// xs is pre-scaled by inv_sqrt_out, agg must be pre-zeroed.
__global__ void prop_kernel(const float4* __restrict__ xs,
                            const int* __restrict__ src,
                            const int* __restrict__ dst,
                            float* __restrict__ agg, int total) {
    int i = blockIdx.x * blockDim.x + threadIdx.x;
    if (i >= total) return;
    unsigned u = (unsigned)i;
    unsigned e = u / 25u;
    unsigned j = u - e * 25u;
    int s = src[e];
    int d = dst[e];
    float4 v = xs[(unsigned)s * 25u + j];
    float* p = agg + ((unsigned)d * 100u + j * 4u);
    asm volatile("red.global.add.v4.f32 [%0], {%1,%2,%3,%4};"
                 :: "l"(p), "f"(v.x), "f"(v.y), "f"(v.z), "f"(v.w)
                 : "memory");
}

// ---------------- GEMM: C = ((sin .* A) @ W + b) .* sout  (or pool-atomic) -
// N = 100 or 200. W fully staged in shared. 256 threads = 8 warps.
// Warp processes 4 rows; lanes 0..24 own N/25 output cols each.
// A values broadcast via shuffle.
template <int N, bool POOL>
__global__ void gemm_kernel(const float* __restrict__ A,
                            const float* __restrict__ W,
                            const float* __restrict__ bias,
                            const float* __restrict__ sin_,
                            const float* __restrict__ sout,
                            float* __restrict__ Cout,
                            const int* __restrict__ gid,
                            int M, int K) {
    extern __shared__ float Wsh[];
    constexpr int CPL = N / 25;  // cols per lane: 4 or 8
    int tid = threadIdx.x;

    // stage W into shared
    {
        int tot4 = (K * N) >> 2;
        const float4* W4 = (const float4*)W;
        float4* Wsh4 = (float4*)Wsh;
        for (int i = tid; i < tot4; i += blockDim.x) Wsh4[i] = W4[i];
    }
    __syncthreads();

    int warp = tid >> 5, lane = tid & 31;
    int c0 = lane * CPL;
    bool active = lane < 25;

    for (int rbase = (blockIdx.x * 8 + warp) * 4; rbase < M; rbase += gridDim.x * 32) {
        float acc[4][CPL];
#pragma unroll
        for (int r = 0; r < 4; r++)
#pragma unroll
            for (int j = 0; j < CPL; j++) acc[r][j] = 0.f;

        float sc[4];
#pragma unroll
        for (int r = 0; r < 4; r++) {
            int row = rbase + r;
            sc[r] = (row < M) ? (sin_ ? sin_[row] : 1.0f) : 0.0f;
        }

        int k0 = 0;
        for (; k0 + 32 <= K; k0 += 32) {
            float a[4];
#pragma unroll
            for (int r = 0; r < 4; r++) {
                int row = rbase + r;
                a[r] = (row < M) ? A[row * K + k0 + lane] * sc[r] : 0.f;
            }
#pragma unroll 8
            for (int t = 0; t < 32; t++) {
                float av[4];
#pragma unroll
                for (int r = 0; r < 4; r++) av[r] = __shfl_sync(0xffffffffu, a[r], t);
                if (active) {
#pragma unroll
                    for (int j4 = 0; j4 < CPL; j4 += 4) {
                        float4 wv = *(const float4*)&Wsh[(k0 + t) * N + c0 + j4];
#pragma unroll
                        for (int r = 0; r < 4; r++) {
                            acc[r][j4 + 0] += av[r] * wv.x;
                            acc[r][j4 + 1] += av[r] * wv.y;
                            acc[r][j4 + 2] += av[r] * wv.z;
                            acc[r][j4 + 3] += av[r] * wv.w;
                        }
                    }
                }
            }
        }
        if (k0 < K) {  // K tail (K=100: 4 leftover)
            int rem = K - k0;
            float a[4];
#pragma unroll
            for (int r = 0; r < 4; r++) {
                int row = rbase + r;
                a[r] = (row < M && lane < rem) ? A[row * K + k0 + lane] * sc[r] : 0.f;
            }
            for (int t = 0; t < rem; t++) {
                float av[4];
#pragma unroll
                for (int r = 0; r < 4; r++) av[r] = __shfl_sync(0xffffffffu, a[r], t);
                if (active) {
#pragma unroll
                    for (int j4 = 0; j4 < CPL; j4 += 4) {
                        float4 wv = *(const float4*)&Wsh[(k0 + t) * N + c0 + j4];
#pragma unroll
                        for (int r = 0; r < 4; r++) {
                            acc[r][j4 + 0] += av[r] * wv.x;
                            acc[r][j4 + 1] += av[r] * wv.y;
                            acc[r][j4 + 2] += av[r] * wv.z;
                            acc[r][j4 + 3] += av[r] * wv.w;
                        }
                    }
                }
            }
        }

        // epilogue
        if (active) {
            if (!POOL) {
#pragma unroll
                for (int r = 0; r < 4; r++) {
                    int row = rbase + r;
                    if (row < M) {
                        float so = sout ? sout[row] : 1.0f;
#pragma unroll
                        for (int j4 = 0; j4 < CPL; j4 += 4) {
                            float4 bv = *(const float4*)&bias[c0 + j4];
                            float4 v;
                            v.x = (acc[r][j4 + 0] + bv.x) * so;
                            v.y = (acc[r][j4 + 1] + bv.y) * so;
                            v.z = (acc[r][j4 + 2] + bv.z) * so;
                            v.w = (acc[r][j4 + 3] + bv.w) * so;
                            *(float4*)&Cout[row * N + c0 + j4] = v;
                        }
                    }
                }
            } else {
#pragma unroll
                for (int r = 0; r < 4; r++) {
                    int row = rbase + r;
                    if (row < M) {
                        int g = gid[row];
#pragma unroll
                        for (int j4 = 0; j4 < CPL; j4 += 4) {
                            float4 bv = *(const float4*)&bias[c0 + j4];
                            float x0 = acc[r][j4 + 0] + bv.x;
                            float x1 = acc[r][j4 + 1] + bv.y;
                            float x2 = acc[r][j4 + 2] + bv.z;
                            float x3 = acc[r][j4 + 3] + bv.w;
                            float* p = &Cout[g * N + c0 + j4];
                            asm volatile("red.global.add.v4.f32 [%0], {%1,%2,%3,%4};"
                                         :: "l"(p), "f"(x0), "f"(x1), "f"(x2), "f"(x3)
                                         : "memory");
                        }
                    }
                }
            }
        }
    }
}

// ---------------- final: out[g,c] = (pool[g,:]/cnt[g]) @ Wc + bc ----------
__global__ void final_kernel(const float* __restrict__ Wc, const float* __restrict__ bc,
                             float* __restrict__ out, int K2, int C) {
    __shared__ float p[H2];
    int g = blockIdx.x;
    float invc = 1.0f / fmaxf(g_cnt[g], 1.0f);
    for (int i = threadIdx.x; i < K2; i += blockDim.x) p[i] = g_pool[g * K2 + i] * invc;
    __syncthreads();
    int c = threadIdx.x;
    if (c < C) {
        float acc = bc[c];
        for (int k = 0; k < K2; k++) acc += p[k] * Wc[k * C + c];
        out[g * C + c] = acc;
    }
}

// ---------------- launch ---------------------------------------------------
extern "C" void kernel_launch(void* const* d_in, const int* in_sizes, int n_in,
                              void* d_out, int out_size) {
    const float* fsnet = (const float*)d_in[0];
    const int*   src   = (const int*)d_in[1];
    const int*   dst   = (const int*)d_in[2];
    const int*   gid   = (const int*)d_in[3];
    const float* W_ext = (const float*)d_in[4];
    const float* b_ext = (const float*)d_in[5];
    const float* W1    = (const float*)d_in[6];
    const float* b1    = (const float*)d_in[7];
    const float* W2    = (const float*)d_in[8];
    const float* b2    = (const float*)d_in[9];
    const float* Wc    = (const float*)d_in[10];
    const float* bc    = (const float*)d_in[11];
    float* out = (float*)d_out;

    int n   = in_sizes[3];           // 50000 nodes (graph_id length)
    int E   = in_sizes[1];           // 800000 edges
    int RAW = in_sizes[4] / LAT;     // 256

    float *bufA, *bufB, *inv_out, *inv_in, *pool, *cnt;
    cudaGetSymbolAddress((void**)&bufA,    g_bufA);
    cudaGetSymbolAddress((void**)&bufB,    g_bufB);
    cudaGetSymbolAddress((void**)&inv_out, g_inv_out);
    cudaGetSymbolAddress((void**)&inv_in,  g_inv_in);
    cudaGetSymbolAddress((void**)&pool,    g_pool);
    cudaGetSymbolAddress((void**)&cnt,     g_cnt);

    cudaFuncSetAttribute(gemm_kernel<100, false>,
                         cudaFuncAttributeMaxDynamicSharedMemorySize, RAW * LAT * 4);
    cudaFuncSetAttribute(gemm_kernel<200, true>,
                         cudaFuncAttributeMaxDynamicSharedMemorySize, LAT * H2 * 4);

    // zero degree accumulators, pooled sums, counts
    zero_kernel<<<(n / 4 + 255) / 256, 256>>>((float4*)inv_out, n / 4);
    zero_kernel<<<(n / 4 + 255) / 256, 256>>>((float4*)inv_in, n / 4);
    zero_kernel<<<(NGRAPH * H2 / 4 + 255) / 256, 256>>>((float4*)pool, NGRAPH * H2 / 4);
    zero_kernel<<<1, 64>>>((float4*)cnt, NGRAPH / 4);

    degree_kernel<<<(E + 255) / 256, 256>>>(src, dst, E);
    rsqrt_kernel<<<(n + 255) / 256, 256>>>(n);

    int gblocks = (n + 31) / 32;

    // xs0 = (fsnet @ W_ext + b_ext) * inv_sqrt_out      -> bufA
    gemm_kernel<100, false><<<gblocks, 256, RAW * LAT * 4>>>(
        fsnet, W_ext, b_ext, nullptr, inv_out, bufA, nullptr, n, RAW);

    // prop1: bufB = scatter-add(bufA[src] -> dst)
    int nb4 = n * LAT / 4;
    zero_kernel<<<(nb4 + 255) / 256, 256>>>((float4*)bufB, nb4);
    int ptotal = E * 25;
    prop_kernel<<<(ptotal + 255) / 256, 256>>>((const float4*)bufA, src, dst, bufB, ptotal);

    // xs1 = ((bufB * inv_in) @ W1 + b1) * inv_out       -> bufA
    gemm_kernel<100, false><<<gblocks, 256, LAT * LAT * 4>>>(
        bufB, W1, b1, inv_in, inv_out, bufA, nullptr, n, LAT);

    // prop2
    zero_kernel<<<(nb4 + 255) / 256, 256>>>((float4*)bufB, nb4);
    prop_kernel<<<(ptotal + 255) / 256, 256>>>((const float4*)bufA, src, dst, bufB, ptotal);

    // h2 = (bufB * inv_in) @ W2 + b2, pooled by graph into g_pool (atomics)
    gemm_kernel<200, true><<<gblocks, 256, LAT * H2 * 4>>>(
        bufB, W2, b2, inv_in, nullptr, pool, gid, n, LAT);

    count_kernel<<<(n + 255) / 256, 256>>>(gid, n);

    // out = (pool / cnt) @ Wc + bc
    final_kernel<<<NGRAPH, 64>>>(Wc, bc, out, H2, NCLASS);
}

// round 2
// speedup vs baseline: 1.1254x; 1.1254x over previous
#include <cuda_runtime.h>
#include <cstdint>

#define MAX_NODES 50000
#define LAT       100
#define NGRAPH    256
#define H2        200
#define NCLASS    55
#define MAX_EDGES 800000

// ---------------- scratch (device globals) ---------------------------------
__device__ __align__(16) float g_bufA[MAX_NODES * LAT];
__device__ __align__(16) float g_bufB[MAX_NODES * LAT];
__device__ __align__(16) float g_inv_out[MAX_NODES];
__device__ __align__(16) float g_inv_in[MAX_NODES];
__device__ __align__(16) int   g_off[MAX_NODES + 16];
__device__ __align__(16) int   g_cur[MAX_NODES];
__device__ __align__(16) int   g_csr[MAX_EDGES];

// packed zero region: [0,50000) out_deg(f32), [50000,100000) deg_in(i32),
// [100000,151200) pool, [151200,151456) cnt
#define ZR_OUTDEG 0
#define ZR_DEGIN  50000
#define ZR_POOL   100000
#define ZR_CNT    151200
#define ZR_TOTAL  151456
__device__ __align__(16) float g_zregion[ZR_TOTAL];

// ---------------- small kernels -------------------------------------------
__global__ void zero_kernel(float4* p, int n4) {
    int i = blockIdx.x * blockDim.x + threadIdx.x;
    float4 z = make_float4(0.f, 0.f, 0.f, 0.f);
    for (; i < n4; i += gridDim.x * blockDim.x) p[i] = z;
}

__global__ void degree_kernel(const int* __restrict__ src, const int* __restrict__ dst, int E) {
    float* out_deg = g_zregion + ZR_OUTDEG;
    int*   deg_in  = (int*)(g_zregion + ZR_DEGIN);
    int i = blockIdx.x * blockDim.x + threadIdx.x;
    if (i < E) {
        atomicAdd(&out_deg[src[i]], 1.0f);
        atomicAdd(&deg_in[dst[i]], 1);
    }
}

// single-block exclusive scan of deg_in -> off/cur; also inv_in/inv_out rsqrt
__global__ void scan_kernel(int n) {
    __shared__ int warp_sums[32];
    __shared__ int s_carry;
    const float* out_deg = g_zregion + ZR_OUTDEG;
    const int*   deg_in  = (const int*)(g_zregion + ZR_DEGIN);
    int tid = threadIdx.x, lane = tid & 31, warp = tid >> 5;
    if (tid == 0) s_carry = 0;
    __syncthreads();
    for (int base = 0; base < n; base += 1024) {
        int i = base + tid;
        int v = (i < n) ? deg_in[i] : 0;
        if (i < n) {
            g_inv_in[i]  = rsqrtf(fmaxf((float)v, 1.0f));
            g_inv_out[i] = rsqrtf(fmaxf(out_deg[i], 1.0f));
        }
        // inclusive warp scan
        int s = v;
#pragma unroll
        for (int d = 1; d < 32; d <<= 1) {
            int t = __shfl_up_sync(0xffffffffu, s, d);
            if (lane >= d) s += t;
        }
        if (lane == 31) warp_sums[warp] = s;
        __syncthreads();
        if (warp == 0) {
            int ws = warp_sums[lane];
#pragma unroll
            for (int d = 1; d < 32; d <<= 1) {
                int t = __shfl_up_sync(0xffffffffu, ws, d);
                if (lane >= d) ws += t;
            }
            warp_sums[lane] = ws;
        }
        __syncthreads();
        int wprefix = (warp > 0) ? warp_sums[warp - 1] : 0;
        int incl = s + wprefix;
        int excl = incl - v + s_carry;
        if (i < n) { g_off[i] = excl; g_cur[i] = excl; }
        int chunk_total = warp_sums[31];
        __syncthreads();
        if (tid == 0) s_carry += chunk_total;
        __syncthreads();
    }
    if (tid == 0) g_off[n] = s_carry;
}

__global__ void scatter_kernel(const int* __restrict__ src, const int* __restrict__ dst, int E) {
    int i = blockIdx.x * blockDim.x + threadIdx.x;
    if (i < E) {
        int p = atomicAdd(&g_cur[dst[i]], 1);
        g_csr[p] = src[i];
    }
}

__global__ void count_kernel(const int* __restrict__ gid, int n) {
    float* cnt = g_zregion + ZR_CNT;
    int i = blockIdx.x * blockDim.x + threadIdx.x;
    if (i < n) atomicAdd(&cnt[gid[i]], 1.0f);
}

// ---------------- CSR propagation: agg[i,:] = sum_{e in in(i)} xs[csr[e],:] -
// one warp per dst node; lanes 0..24 each own one float4 chunk.
__global__ void prop_csr_kernel(const float4* __restrict__ xs,
                                float4* __restrict__ agg, int n) {
    int warp = (blockIdx.x * blockDim.x + threadIdx.x) >> 5;
    int lane = threadIdx.x & 31;
    if (warp >= n) return;
    int b = g_off[warp], e = g_off[warp + 1];
    bool act = lane < 25;
    float4 a0 = make_float4(0.f, 0.f, 0.f, 0.f);
    float4 a1 = a0, a2 = a0, a3 = a0;
    unsigned base = (unsigned)lane;
    int k = b;
    for (; k + 4 <= e; k += 4) {
        int s0 = g_csr[k], s1 = g_csr[k + 1], s2 = g_csr[k + 2], s3 = g_csr[k + 3];
        if (act) {
            float4 v0 = xs[(unsigned)s0 * 25u + base];
            float4 v1 = xs[(unsigned)s1 * 25u + base];
            float4 v2 = xs[(unsigned)s2 * 25u + base];
            float4 v3 = xs[(unsigned)s3 * 25u + base];
            a0.x += v0.x; a0.y += v0.y; a0.z += v0.z; a0.w += v0.w;
            a1.x += v1.x; a1.y += v1.y; a1.z += v1.z; a1.w += v1.w;
            a2.x += v2.x; a2.y += v2.y; a2.z += v2.z; a2.w += v2.w;
            a3.x += v3.x; a3.y += v3.y; a3.z += v3.z; a3.w += v3.w;
        }
    }
    for (; k < e; k++) {
        int s0 = g_csr[k];
        if (act) {
            float4 v0 = xs[(unsigned)s0 * 25u + base];
            a0.x += v0.x; a0.y += v0.y; a0.z += v0.z; a0.w += v0.w;
        }
    }
    if (act) {
        a0.x += a1.x + a2.x + a3.x;
        a0.y += a1.y + a2.y + a3.y;
        a0.z += a1.z + a2.z + a3.z;
        a0.w += a1.w + a2.w + a3.w;
        agg[(unsigned)warp * 25u + base] = a0;
    }
}

// ---------------- GEMM: C = ((sin .* A) @ W + b) .* sout  (or pool-atomic) -
template <int N, bool POOL>
__global__ void gemm_kernel(const float* __restrict__ A,
                            const float* __restrict__ W,
                            const float* __restrict__ bias,
                            const float* __restrict__ sin_,
                            const float* __restrict__ sout,
                            float* __restrict__ Cout,
                            const int* __restrict__ gid,
                            int M, int K) {
    extern __shared__ float Wsh[];
    constexpr int CPL = N / 25;
    int tid = threadIdx.x;
    {
        int tot4 = (K * N) >> 2;
        const float4* W4 = (const float4*)W;
        float4* Wsh4 = (float4*)Wsh;
        for (int i = tid; i < tot4; i += blockDim.x) Wsh4[i] = W4[i];
    }
    __syncthreads();

    int warp = tid >> 5, lane = tid & 31;
    int c0 = lane * CPL;
    bool active = lane < 25;

    for (int rbase = (blockIdx.x * 8 + warp) * 4; rbase < M; rbase += gridDim.x * 32) {
        float acc[4][CPL];
#pragma unroll
        for (int r = 0; r < 4; r++)
#pragma unroll
            for (int j = 0; j < CPL; j++) acc[r][j] = 0.f;

        float sc[4];
#pragma unroll
        for (int r = 0; r < 4; r++) {
            int row = rbase + r;
            sc[r] = (row < M) ? (sin_ ? sin_[row] : 1.0f) : 0.0f;
        }

        int k0 = 0;
        for (; k0 + 32 <= K; k0 += 32) {
            float a[4];
#pragma unroll
            for (int r = 0; r < 4; r++) {
                int row = rbase + r;
                a[r] = (row < M) ? A[row * K + k0 + lane] * sc[r] : 0.f;
            }
#pragma unroll 8
            for (int t = 0; t < 32; t++) {
                float av[4];
#pragma unroll
                for (int r = 0; r < 4; r++) av[r] = __shfl_sync(0xffffffffu, a[r], t);
                if (active) {
#pragma unroll
                    for (int j4 = 0; j4 < CPL; j4 += 4) {
                        float4 wv = *(const float4*)&Wsh[(k0 + t) * N + c0 + j4];
#pragma unroll
                        for (int r = 0; r < 4; r++) {
                            acc[r][j4 + 0] += av[r] * wv.x;
                            acc[r][j4 + 1] += av[r] * wv.y;
                            acc[r][j4 + 2] += av[r] * wv.z;
                            acc[r][j4 + 3] += av[r] * wv.w;
                        }
                    }
                }
            }
        }
        if (k0 < K) {
            int rem = K - k0;
            float a[4];
#pragma unroll
            for (int r = 0; r < 4; r++) {
                int row = rbase + r;
                a[r] = (row < M && lane < rem) ? A[row * K + k0 + lane] * sc[r] : 0.f;
            }
            for (int t = 0; t < rem; t++) {
                float av[4];
#pragma unroll
                for (int r = 0; r < 4; r++) av[r] = __shfl_sync(0xffffffffu, a[r], t);
                if (active) {
#pragma unroll
                    for (int j4 = 0; j4 < CPL; j4 += 4) {
                        float4 wv = *(const float4*)&Wsh[(k0 + t) * N + c0 + j4];
#pragma unroll
                        for (int r = 0; r < 4; r++) {
                            acc[r][j4 + 0] += av[r] * wv.x;
                            acc[r][j4 + 1] += av[r] * wv.y;
                            acc[r][j4 + 2] += av[r] * wv.z;
                            acc[r][j4 + 3] += av[r] * wv.w;
                        }
                    }
                }
            }
        }

        if (active) {
            if (!POOL) {
#pragma unroll
                for (int r = 0; r < 4; r++) {
                    int row = rbase + r;
                    if (row < M) {
                        float so = sout ? sout[row] : 1.0f;
#pragma unroll
                        for (int j4 = 0; j4 < CPL; j4 += 4) {
                            float4 bv = *(const float4*)&bias[c0 + j4];
                            float4 v;
                            v.x = (acc[r][j4 + 0] + bv.x) * so;
                            v.y = (acc[r][j4 + 1] + bv.y) * so;
                            v.z = (acc[r][j4 + 2] + bv.z) * so;
                            v.w = (acc[r][j4 + 3] + bv.w) * so;
                            *(float4*)&Cout[row * N + c0 + j4] = v;
                        }
                    }
                }
            } else {
#pragma unroll
                for (int r = 0; r < 4; r++) {
                    int row = rbase + r;
                    if (row < M) {
                        int g = gid[row];
#pragma unroll
                        for (int j4 = 0; j4 < CPL; j4 += 4) {
                            float4 bv = *(const float4*)&bias[c0 + j4];
                            float x0 = acc[r][j4 + 0] + bv.x;
                            float x1 = acc[r][j4 + 1] + bv.y;
                            float x2 = acc[r][j4 + 2] + bv.z;
                            float x3 = acc[r][j4 + 3] + bv.w;
                            float* p = &Cout[g * N + c0 + j4];
                            asm volatile("red.global.add.v4.f32 [%0], {%1,%2,%3,%4};"
                                         :: "l"(p), "f"(x0), "f"(x1), "f"(x2), "f"(x3)
                                         : "memory");
                        }
                    }
                }
            }
        }
    }
}

// ---------------- final: out[g,c] = (pool[g,:]/cnt[g]) @ Wc + bc ----------
__global__ void final_kernel(const float* __restrict__ Wc, const float* __restrict__ bc,
                             float* __restrict__ out, int K2, int C) {
    __shared__ float p[H2];
    const float* pool = g_zregion + ZR_POOL;
    const float* cnt  = g_zregion + ZR_CNT;
    int g = blockIdx.x;
    float invc = 1.0f / fmaxf(cnt[g], 1.0f);
    for (int i = threadIdx.x; i < K2; i += blockDim.x) p[i] = pool[g * K2 + i] * invc;
    __syncthreads();
    int c = threadIdx.x;
    if (c < C) {
        float acc = bc[c];
        for (int k = 0; k < K2; k++) acc += p[k] * Wc[k * C + c];
        out[g * C + c] = acc;
    }
}

// ---------------- launch ---------------------------------------------------
extern "C" void kernel_launch(void* const* d_in, const int* in_sizes, int n_in,
                              void* d_out, int out_size) {
    const float* fsnet = (const float*)d_in[0];
    const int*   src   = (const int*)d_in[1];
    const int*   dst   = (const int*)d_in[2];
    const int*   gid   = (const int*)d_in[3];
    const float* W_ext = (const float*)d_in[4];
    const float* b_ext = (const float*)d_in[5];
    const float* W1    = (const float*)d_in[6];
    const float* b1    = (const float*)d_in[7];
    const float* W2    = (const float*)d_in[8];
    const float* b2    = (const float*)d_in[9];
    const float* Wc    = (const float*)d_in[10];
    const float* bc    = (const float*)d_in[11];
    float* out = (float*)d_out;

    int n   = in_sizes[3];
    int E   = in_sizes[1];
    int RAW = in_sizes[4] / LAT;

    float *bufA, *bufB, *inv_out, *inv_in, *zreg, *pool;
    cudaGetSymbolAddress((void**)&bufA,    g_bufA);
    cudaGetSymbolAddress((void**)&bufB,    g_bufB);
    cudaGetSymbolAddress((void**)&inv_out, g_inv_out);
    cudaGetSymbolAddress((void**)&inv_in,  g_inv_in);
    cudaGetSymbolAddress((void**)&zreg,    g_zregion);
    pool = zreg + ZR_POOL;

    cudaFuncSetAttribute(gemm_kernel<100, false>,
                         cudaFuncAttributeMaxDynamicSharedMemorySize, RAW * LAT * 4);
    cudaFuncSetAttribute(gemm_kernel<200, true>,
                         cudaFuncAttributeMaxDynamicSharedMemorySize, LAT * H2 * 4);

    // 1. zero packed scratch (degrees + pool + cnt)
    zero_kernel<<<148, 256>>>((float4*)zreg, ZR_TOTAL / 4);

    // 2. degrees (float out-deg histogram, int in-deg histogram)
    degree_kernel<<<(E + 255) / 256, 256>>>(src, dst, E);

    // 3. offsets + rsqrt scaling factors (single block scan)
    scan_kernel<<<1, 1024>>>(n);

    // 4. CSR scatter (by dst)
    scatter_kernel<<<(E + 255) / 256, 256>>>(src, dst, E);

    // per-graph node counts (independent)
    count_kernel<<<(n + 255) / 256, 256>>>(gid, n);

    // 5. xs0 = (fsnet @ W_ext + b_ext) * inv_sqrt_out -> bufA
    gemm_kernel<100, false><<<296, 256, RAW * LAT * 4>>>(
        fsnet, W_ext, b_ext, nullptr, inv_out, bufA, nullptr, n, RAW);

    // 6. prop1: bufB[i] = sum over in-edges of bufA
    int pblocks = (n * 32 + 255) / 256;
    prop_csr_kernel<<<pblocks, 256>>>((const float4*)bufA, (float4*)bufB, n);

    // 7. xs1 = ((bufB * inv_in) @ W1 + b1) * inv_out -> bufA
    gemm_kernel<100, false><<<592, 256, LAT * LAT * 4>>>(
        bufB, W1, b1, inv_in, inv_out, bufA, nullptr, n, LAT);

    // 8. prop2
    prop_csr_kernel<<<pblocks, 256>>>((const float4*)bufA, (float4*)bufB, n);

    // 9. h2 = (bufB * inv_in) @ W2 + b2, pooled by graph into pool (atomics)
    gemm_kernel<200, true><<<296, 256, LAT * H2 * 4>>>(
        bufB, W2, b2, inv_in, nullptr, pool, gid, n, LAT);

    // 10. out = (pool / cnt) @ Wc + bc
    final_kernel<<<NGRAPH, 64>>>(Wc, bc, out, H2, NCLASS);
}